// round 10
// baseline (speedup 1.0000x reference)
#include <cuda_runtime.h>
#include <cstdint>

#define T_HASH 524288      // 2^19 -> mod == & mask, low-32-bit arithmetic suffices
#define HMASK  (T_HASH - 1)
#define PI2    2654435761u
#define PI3    805459861u
#define NPTS_MAX 524288

// 64 MB feature scratch: [level][point] float2, coalesced on both sides.
__device__ __align__(16) float2 g_feats[16][NPTS_MAX];

// ---- packed f32x2 helpers (Blackwell FFMA2 is only reachable via PTX) ----
__device__ __forceinline__ unsigned long long pk2(float v) {
    unsigned long long r;
    asm("mov.b64 %0, {%1, %1};" : "=l"(r) : "f"(v));
    return r;
}
__device__ __forceinline__ unsigned long long fma2(unsigned long long a,
                                                   unsigned long long b,
                                                   unsigned long long c) {
    unsigned long long d;
    asm("fma.rn.f32x2 %0, %1, %2, %3;" : "=l"(d) : "l"(a), "l"(b), "l"(c));
    return d;
}
__device__ __forceinline__ void unpk(unsigned long long v, float& a, float& b) {
    asm("mov.b64 {%0, %1}, %2;" : "=f"(a), "=f"(b) : "l"(v));
}

// constant memory: layer 1a only stays on the LDC port (512 LDC.128/pt).
#define OW1A 0       // [32,64]  2048
#define OB1A 2048    // [64]
#define CWTOT 2112

__constant__ __align__(16) float cW[CWTOT];

// shared-memory layout for the remaining layers (read via broadcast LDS.128,
// LSU port — parallel with the constant port). float offsets, 16B-aligned.
#define SW1B 0       // [64,16]  1024
#define SB1B 1024    // [16]
#define SW2A 1040    // [43,64]  2752
#define SB2A 3792    // [64]
#define SW2B 3856    // [64,64]  4096
#define SB2B 7952    // [64]
#define SW2C 8016    // [64,3]   192
#define SB2C 8208    // [3]
#define SWTOT 8212   // 32.8 KB -> 4 CTAs/SM = 131 KB < 228 KB

// ======================= kernel 1: hash-grid gather =======================
// Low register count -> high occupancy -> scattered-L2 latency hidden by warps.
__global__ __launch_bounds__(256)
void ngp_gather_kernel(const float* __restrict__ x,
                       const float* __restrict__ tables, int n)
{
    int i = blockIdx.x * blockDim.x + threadIdx.x;
    if (i >= n) return;

    float xu0 = __fdiv_rn(x[3 * i + 0], 3.0f) + 0.5f;
    float xu1 = __fdiv_rn(x[3 * i + 1], 3.0f) + 0.5f;
    float xu2 = __fdiv_rn(x[3 * i + 2], 3.0f) + 0.5f;

    const float NLv[16] = {16.f, 22.f, 30.f, 42.f, 58.f, 80.f, 110.f, 152.f,
                           209.f, 288.f, 397.f, 547.f, 754.f, 1039.f, 1432.f, 1974.f};
    const float2* tb2 = (const float2*)tables;

    #pragma unroll
    for (int l = 0; l < 16; l++) {
        float nl = NLv[l];
        float p0 = xu0 * nl, p1 = xu1 * nl, p2 = xu2 * nl;
        float f0 = floorf(p0), f1 = floorf(p1), f2 = floorf(p2);
        float r0 = p0 - f0, r1 = p1 - f1, r2 = p2 - f2;
        float a0 = 1.0f - r0, a1 = 1.0f - r1, a2 = 1.0f - r2;

        // int64 hash ≡ low-32-bit hash because T = 2^19 and % T picks low bits
        unsigned hx0 = (unsigned)(int)f0;                 // * 1
        unsigned hy0 = (unsigned)(int)f1 * PI2;
        unsigned hz0 = (unsigned)(int)f2 * PI3;
        unsigned hx1 = hx0 + (r0 > 0.0f ? 1u   : 0u);     // ceil variant
        unsigned hy1 = hy0 + (r1 > 0.0f ? PI2  : 0u);
        unsigned hz1 = hz0 + (r2 > 0.0f ? PI3  : 0u);

        const float2* tbl = tb2 + (size_t)l * T_HASH;
        // issue all 8 loads, then reduce
        float2 t[8];
        #pragma unroll
        for (int k = 0; k < 8; k++) {
            unsigned hh = (((0xE2 >> k) & 1) ? hx1 : hx0)
                        ^ (((0xD4 >> k) & 1) ? hy1 : hy0)
                        ^ (((0xB8 >> k) & 1) ? hz1 : hz0);
            t[k] = __ldg(tbl + (hh & HMASK));
        }
        float acc0 = 0.0f, acc1 = 0.0f;
        #pragma unroll
        for (int k = 0; k < 8; k++) {
            float w = ((k & 1) ? r0 : a0) * ((k & 2) ? r1 : a1) * ((k & 4) ? r2 : a2);
            acc0 = fmaf(w, t[k].x, acc0);
            acc1 = fmaf(w, t[k].y, acc1);
        }
        g_feats[l][i] = make_float2(acc0, acc1);
    }
}

// ======================= kernel 2: fused MLPs =======================
__global__ __launch_bounds__(128)
void ngp_mlp_kernel(const float* __restrict__ x, const float* __restrict__ ddir,
                    const float* __restrict__ w1b, const float* __restrict__ b1b,
                    const float* __restrict__ w2a, const float* __restrict__ b2a,
                    const float* __restrict__ w2b, const float* __restrict__ b2b,
                    const float* __restrict__ w2c, const float* __restrict__ b2c,
                    float* __restrict__ out, int n)
{
    __shared__ __align__(16) float sw[SWTOT];
    {
        const float* srcs[8] = {w1b, b1b, w2a, b2a, w2b, b2b, w2c, b2c};
        const int offs[8]    = {SW1B, SB1B, SW2A, SB2A, SW2B, SB2B, SW2C, SB2C};
        const int lens[8]    = {1024, 16, 2752, 64, 4096, 64, 192, 3};
        #pragma unroll
        for (int s = 0; s < 8; s++)
            for (int idx = threadIdx.x; idx < lens[s]; idx += blockDim.x)
                sw[offs[s] + idx] = srcs[s][idx];
    }
    __syncthreads();

    int i = blockIdx.x * blockDim.x + threadIdx.x;
    if (i >= n) return;

    float x0 = x[3 * i + 0], x1 = x[3 * i + 1], x2 = x[3 * i + 2];
    float d0 = ddir[3 * i + 0], d1 = ddir[3 * i + 1], d2 = ddir[3 * i + 2];

    float xs0 = __fdiv_rn(x0, 3.0f), xs1 = __fdiv_rn(x1, 3.0f), xs2 = __fdiv_rn(x2, 3.0f);
    bool mask = (fabsf(xs0) < 0.5f) && (fabsf(xs1) < 0.5f) && (fabsf(xs2) < 0.5f);

    // coalesced feature reload
    float feats[32];
    #pragma unroll
    for (int l = 0; l < 16; l++) {
        float2 f = g_feats[l][i];
        feats[2 * l + 0] = f.x;
        feats[2 * l + 1] = f.y;
    }

    // ---------------- MLP layer 1a: 32 -> 64, relu (weights: constant port) ----
    unsigned long long acc[32];
    {
        const unsigned long long* pb = (const unsigned long long*)(cW + OB1A);
        #pragma unroll
        for (int j = 0; j < 32; j++) acc[j] = pb[j];
        #pragma unroll 4
        for (int k = 0; k < 32; k++) {
            unsigned long long bv = pk2(feats[k]);
            const ulonglong2* wr = (const ulonglong2*)(cW + OW1A + k * 64);
            #pragma unroll
            for (int j = 0; j < 16; j++) {
                ulonglong2 ww = wr[j];
                acc[2 * j + 0] = fma2(bv, ww.x, acc[2 * j + 0]);
                acc[2 * j + 1] = fma2(bv, ww.y, acc[2 * j + 1]);
            }
        }
    }
    float h1[64];
    #pragma unroll
    for (int j = 0; j < 32; j++) {
        float a, b;
        unpk(acc[j], a, b);
        h1[2 * j + 0] = fmaxf(a, 0.0f);
        h1[2 * j + 1] = fmaxf(b, 0.0f);
    }

    // ---------------- MLP layer 1b: 64 -> 16 (weights: smem/LSU port) --------
    float hh16[16];
    {
        unsigned long long acc2[8];
        const unsigned long long* pb = (const unsigned long long*)(sw + SB1B);
        #pragma unroll
        for (int j = 0; j < 8; j++) acc2[j] = pb[j];
        #pragma unroll 8
        for (int k = 0; k < 64; k++) {
            unsigned long long bv = pk2(h1[k]);
            const ulonglong2* wr = (const ulonglong2*)(sw + SW1B + k * 16);
            #pragma unroll
            for (int j = 0; j < 4; j++) {
                ulonglong2 ww = wr[j];
                acc2[2 * j + 0] = fma2(bv, ww.x, acc2[2 * j + 0]);
                acc2[2 * j + 1] = fma2(bv, ww.y, acc2[2 * j + 1]);
            }
        }
        #pragma unroll
        for (int j = 0; j < 8; j++) unpk(acc2[j], hh16[2 * j], hh16[2 * j + 1]);
    }

    float sigma = mask ? __expf(hh16[0]) : 0.0f;

    // ---------------- z = [h(16), d(3), sin/cos posenc(24)] ----------------
    float z[43];
    #pragma unroll
    for (int j = 0; j < 16; j++) z[j] = hh16[j];
    z[16] = d0; z[17] = d1; z[18] = d2;
    #pragma unroll
    for (int q = 0; q < 4; q++) {
        float m = (float)(1 << q);
        float s, c;
        __sincosf(m * d0, &s, &c); z[19 + 6 * q + 0] = s; z[22 + 6 * q + 0] = c;
        __sincosf(m * d1, &s, &c); z[19 + 6 * q + 1] = s; z[22 + 6 * q + 1] = c;
        __sincosf(m * d2, &s, &c); z[19 + 6 * q + 2] = s; z[22 + 6 * q + 2] = c;
    }

    // ---------------- MLP layer 2a: 43 -> 64, relu (smem) ----------------
    {
        const unsigned long long* pb = (const unsigned long long*)(sw + SB2A);
        #pragma unroll
        for (int j = 0; j < 32; j++) acc[j] = pb[j];
        #pragma unroll 4
        for (int k = 0; k < 43; k++) {
            unsigned long long bv = pk2(z[k]);
            const ulonglong2* wr = (const ulonglong2*)(sw + SW2A + k * 64);
            #pragma unroll
            for (int j = 0; j < 16; j++) {
                ulonglong2 ww = wr[j];
                acc[2 * j + 0] = fma2(bv, ww.x, acc[2 * j + 0]);
                acc[2 * j + 1] = fma2(bv, ww.y, acc[2 * j + 1]);
            }
        }
        #pragma unroll
        for (int j = 0; j < 32; j++) {
            float a, b;
            unpk(acc[j], a, b);
            h1[2 * j + 0] = fmaxf(a, 0.0f);   // reuse h1 as za[64]
            h1[2 * j + 1] = fmaxf(b, 0.0f);
        }
    }

    // ---------------- MLP layer 2b: 64 -> 64, relu (smem) ----------------
    float zb[64];
    {
        const unsigned long long* pb = (const unsigned long long*)(sw + SB2B);
        #pragma unroll
        for (int j = 0; j < 32; j++) acc[j] = pb[j];
        #pragma unroll 4
        for (int k = 0; k < 64; k++) {
            unsigned long long bv = pk2(h1[k]);
            const ulonglong2* wr = (const ulonglong2*)(sw + SW2B + k * 64);
            #pragma unroll
            for (int j = 0; j < 16; j++) {
                ulonglong2 ww = wr[j];
                acc[2 * j + 0] = fma2(bv, ww.x, acc[2 * j + 0]);
                acc[2 * j + 1] = fma2(bv, ww.y, acc[2 * j + 1]);
            }
        }
        #pragma unroll
        for (int j = 0; j < 32; j++) {
            float a, b;
            unpk(acc[j], a, b);
            zb[2 * j + 0] = fmaxf(a, 0.0f);
            zb[2 * j + 1] = fmaxf(b, 0.0f);
        }
    }

    // ---------------- MLP layer 2c: 64 -> 3, sigmoid (smem) ----------------
    float c0 = sw[SB2C + 0], c1 = sw[SB2C + 1], c2 = sw[SB2C + 2];
    #pragma unroll 8
    for (int k = 0; k < 64; k++) {
        float v = zb[k];
        c0 = fmaf(v, sw[SW2C + 3 * k + 0], c0);
        c1 = fmaf(v, sw[SW2C + 3 * k + 1], c1);
        c2 = fmaf(v, sw[SW2C + 3 * k + 2], c2);
    }
    c0 = 1.0f / (1.0f + __expf(-c0));
    c1 = 1.0f / (1.0f + __expf(-c1));
    c2 = 1.0f / (1.0f + __expf(-c2));

    out[3 * i + 0] = mask ? c0 : 0.0f;
    out[3 * i + 1] = mask ? c1 : 0.0f;
    out[3 * i + 2] = mask ? c2 : 0.0f;
    out[3 * n + i] = sigma;
}

extern "C" void kernel_launch(void* const* d_in, const int* in_sizes, int n_in,
                              void* d_out, int out_size) {
    const float* x      = (const float*)d_in[0];
    const float* dd     = (const float*)d_in[1];
    const float* tables = (const float*)d_in[2];

    // Stage layer-1a weights into constant memory (D2D async, capturable).
    cudaMemcpyToSymbolAsync(cW, d_in[3], 2048 * sizeof(float),
                            OW1A * sizeof(float), cudaMemcpyDeviceToDevice);
    cudaMemcpyToSymbolAsync(cW, d_in[4], 64 * sizeof(float),
                            OB1A * sizeof(float), cudaMemcpyDeviceToDevice);

    int n = in_sizes[0] / 3;

    int t1 = 256;
    ngp_gather_kernel<<<(n + t1 - 1) / t1, t1>>>(x, tables, n);

    int t2 = 128;
    ngp_mlp_kernel<<<(n + t2 - 1) / t2, t2>>>(
        x, dd,
        (const float*)d_in[5], (const float*)d_in[6],
        (const float*)d_in[7], (const float*)d_in[8],
        (const float*)d_in[9], (const float*)d_in[10],
        (const float*)d_in[11], (const float*)d_in[12],
        (float*)d_out, n);
}

// round 13
// speedup vs baseline: 1.1711x; 1.1711x over previous
#include <cuda_runtime.h>
#include <cstdint>

#define T_HASH 524288
#define HMASK  (T_HASH - 1)
#define PI2    2654435761u
#define PI3    805459861u
#define NPTS_MAX 524288

// 64 MB feature scratch: [level][point] float2, coalesced on both sides.
__device__ __align__(16) float2 g_feats[16][NPTS_MAX];

// ---- tf32 helpers ----
__device__ __forceinline__ unsigned f2tf(float f) {
    unsigned u;
    asm("cvt.rna.tf32.f32 %0, %1;" : "=r"(u) : "f"(f));
    return u;
}
__device__ __forceinline__ void mma_tf32(float& c0, float& c1, float& c2, float& c3,
                                         unsigned a0, unsigned a1, unsigned a2, unsigned a3,
                                         unsigned b0, unsigned b1) {
    asm("mma.sync.aligned.m16n8k8.row.col.f32.tf32.tf32.f32 "
        "{%0,%1,%2,%3},{%4,%5,%6,%7},{%8,%9},{%0,%1,%2,%3};"
        : "+f"(c0), "+f"(c1), "+f"(c2), "+f"(c3)
        : "r"(a0), "r"(a1), "r"(a2), "r"(a3), "r"(b0), "r"(b1));
}

// ---- dynamic smem word-offsets ----
// Transposed weights W_T[n][k] (tf32 bits), row strides padded so B-frag loads
// hit 32 distinct banks: bank = (4g+tg) pattern.
#define OW1AT  0        // uint [64][36]   (w1a [32,64], K=32 pad 36)
#define OW1BT  2304     // uint [16][68]   (w1b [64,16], K=64 pad 68)
#define OW2ATH 3392     // uint [64][52]   (w2a [43,64], K pad 48->52) hi
#define OW2ATL 6720     //                 lo
#define OW2BTH 10048    // uint [64][68]   (w2b [64,64]) hi
#define OW2BTL 14400    //                 lo
#define OW2C   18752    // float [192]
#define OB2C   18944    // float [3]
#define OB1A   18948    // float [64]
#define OB1B   19012    // float [16]
#define OB2A   19028    // float [64]
#define OB2B   19092    // float [64]
#define OACT   19160    // float, per warp 32 rows x stride 68
#define ACT_STRIDE 68
#define ACT_PER_WARP (32 * ACT_STRIDE)           // 2176
#define SMEM_WORDS (OACT + 4 * ACT_PER_WARP)     // 27864
#define SMEM_BYTES (SMEM_WORDS * 4)              // 111456 B -> 2 CTA/SM

// ======================= kernel 1: hash-grid gather =======================
__global__ __launch_bounds__(256)
void ngp_gather_kernel(const float* __restrict__ x,
                       const float* __restrict__ tables, int n)
{
    int i = blockIdx.x * blockDim.x + threadIdx.x;
    if (i >= n) return;

    float xu0 = __fdiv_rn(x[3 * i + 0], 3.0f) + 0.5f;
    float xu1 = __fdiv_rn(x[3 * i + 1], 3.0f) + 0.5f;
    float xu2 = __fdiv_rn(x[3 * i + 2], 3.0f) + 0.5f;

    const float NLv[16] = {16.f, 22.f, 30.f, 42.f, 58.f, 80.f, 110.f, 152.f,
                           209.f, 288.f, 397.f, 547.f, 754.f, 1039.f, 1432.f, 1974.f};
    const float2* tb2 = (const float2*)tables;

    #pragma unroll
    for (int l = 0; l < 16; l++) {
        float nl = NLv[l];
        float p0 = xu0 * nl, p1 = xu1 * nl, p2 = xu2 * nl;
        float f0 = floorf(p0), f1 = floorf(p1), f2 = floorf(p2);
        float r0 = p0 - f0, r1 = p1 - f1, r2 = p2 - f2;
        float a0 = 1.0f - r0, a1 = 1.0f - r1, a2 = 1.0f - r2;

        unsigned hx0 = (unsigned)(int)f0;
        unsigned hy0 = (unsigned)(int)f1 * PI2;
        unsigned hz0 = (unsigned)(int)f2 * PI3;
        unsigned hx1 = hx0 + (r0 > 0.0f ? 1u   : 0u);
        unsigned hy1 = hy0 + (r1 > 0.0f ? PI2  : 0u);
        unsigned hz1 = hz0 + (r2 > 0.0f ? PI3  : 0u);

        const float2* tbl = tb2 + (size_t)l * T_HASH;
        float2 t[8];
        #pragma unroll
        for (int k = 0; k < 8; k++) {
            unsigned hh = (((0xE2 >> k) & 1) ? hx1 : hx0)
                        ^ (((0xD4 >> k) & 1) ? hy1 : hy0)
                        ^ (((0xB8 >> k) & 1) ? hz1 : hz0);
            t[k] = __ldg(tbl + (hh & HMASK));
        }
        float acc0 = 0.0f, acc1 = 0.0f;
        #pragma unroll
        for (int k = 0; k < 8; k++) {
            float w = ((k & 1) ? r0 : a0) * ((k & 2) ? r1 : a1) * ((k & 4) ? r2 : a2);
            acc0 = fmaf(w, t[k].x, acc0);
            acc1 = fmaf(w, t[k].y, acc1);
        }
        g_feats[l][i] = make_float2(acc0, acc1);
    }
}

// ======================= kernel 2: tensor-core MLPs =======================
// 128 threads = 4 warps; each warp owns 32 points (2 M-tiles of m16n8k8 mma).
__global__ __launch_bounds__(128)
void ngp_mlp_kernel(const float* __restrict__ x, const float* __restrict__ ddir,
                    const float* __restrict__ w1a, const float* __restrict__ b1a,
                    const float* __restrict__ w1b, const float* __restrict__ b1b,
                    const float* __restrict__ w2a, const float* __restrict__ b2a,
                    const float* __restrict__ w2b, const float* __restrict__ b2b,
                    const float* __restrict__ w2c, const float* __restrict__ b2c,
                    float* __restrict__ out, int n)
{
    extern __shared__ float sm[];
    unsigned* su = (unsigned*)sm;
    int tid = threadIdx.x;

    // ---- stage weights (transpose + tf32 convert; hi/lo split for layer 2) ----
    for (int idx = tid; idx < 64 * 36; idx += 128) {
        int nn = idx / 36, kk = idx % 36;
        su[OW1AT + idx] = (kk < 32) ? f2tf(w1a[kk * 64 + nn]) : 0u;
    }
    for (int idx = tid; idx < 16 * 68; idx += 128) {
        int nn = idx / 68, kk = idx % 68;
        su[OW1BT + idx] = (kk < 64) ? f2tf(w1b[kk * 16 + nn]) : 0u;
    }
    for (int idx = tid; idx < 64 * 52; idx += 128) {
        int nn = idx / 52, kk = idx % 52;
        float f = (kk < 43) ? w2a[kk * 64 + nn] : 0.0f;
        unsigned h = f2tf(f);
        su[OW2ATH + idx] = h;
        su[OW2ATL + idx] = f2tf(f - __uint_as_float(h));
    }
    for (int idx = tid; idx < 64 * 68; idx += 128) {
        int nn = idx / 68, kk = idx % 68;
        float f = (kk < 64) ? w2b[kk * 64 + nn] : 0.0f;
        unsigned h = f2tf(f);
        su[OW2BTH + idx] = h;
        su[OW2BTL + idx] = f2tf(f - __uint_as_float(h));
    }
    for (int idx = tid; idx < 192; idx += 128) sm[OW2C + idx] = w2c[idx];
    if (tid < 3)  sm[OB2C + tid] = b2c[tid];
    if (tid < 64) { sm[OB1A + tid] = b1a[tid]; sm[OB2A + tid] = b2a[tid]; sm[OB2B + tid] = b2b[tid]; }
    if (tid < 16) sm[OB1B + tid] = b1b[tid];
    __syncthreads();

    const int wid = tid >> 5, ln = tid & 31;
    const int g = ln >> 2, tg = ln & 3;
    const int actB = OACT + wid * ACT_PER_WARP;
    const int pt = blockIdx.x * 128 + wid * 32 + ln;
    const bool valid = (pt < n);

    // per-point scalars
    float d0 = 0.f, d1 = 0.f, d2 = 0.f;
    bool mask = false;
    if (valid) {
        float xs0 = __fdiv_rn(x[3 * pt + 0], 3.0f);
        float xs1 = __fdiv_rn(x[3 * pt + 1], 3.0f);
        float xs2 = __fdiv_rn(x[3 * pt + 2], 3.0f);
        mask = (fabsf(xs0) < 0.5f) && (fabsf(xs1) < 0.5f) && (fabsf(xs2) < 0.5f);
        d0 = ddir[3 * pt + 0]; d1 = ddir[3 * pt + 1]; d2 = ddir[3 * pt + 2];
    }

    // ---- stage this warp's 32x32 feats into act rows ----
    {
        int p = valid ? pt : 0;
        #pragma unroll
        for (int l = 0; l < 16; l++) {
            float2 f = g_feats[l][p];
            sm[actB + ln * ACT_STRIDE + 2 * l + 0] = f.x;
            sm[actB + ln * ACT_STRIDE + 2 * l + 1] = f.y;
        }
    }
    __syncwarp();

    // =============== layer 1a: [32,32]x[32,64], relu, single tf32 ===============
    {
        unsigned au[2][4][4];
        #pragma unroll
        for (int mt = 0; mt < 2; mt++)
            #pragma unroll
            for (int kt = 0; kt < 4; kt++) {
                int r = actB + (mt * 16 + g) * ACT_STRIDE + kt * 8;
                au[mt][kt][0] = f2tf(sm[r + tg]);
                au[mt][kt][1] = f2tf(sm[r + 8 * ACT_STRIDE + tg]);
                au[mt][kt][2] = f2tf(sm[r + tg + 4]);
                au[mt][kt][3] = f2tf(sm[r + 8 * ACT_STRIDE + tg + 4]);
            }
        __syncwarp();
        #pragma unroll
        for (int mt = 0; mt < 2; mt++)
            #pragma unroll
            for (int nt = 0; nt < 8; nt++) {
                float c0 = sm[OB1A + nt * 8 + 2 * tg], c1 = sm[OB1A + nt * 8 + 2 * tg + 1];
                float c2 = c0, c3 = c1;
                #pragma unroll
                for (int kt = 0; kt < 4; kt++) {
                    int wb = OW1AT + (nt * 8 + g) * 36 + kt * 8 + tg;
                    mma_tf32(c0, c1, c2, c3,
                             au[mt][kt][0], au[mt][kt][1], au[mt][kt][2], au[mt][kt][3],
                             su[wb], su[wb + 4]);
                }
                int r = actB + (mt * 16 + g) * ACT_STRIDE + nt * 8 + 2 * tg;
                sm[r] = fmaxf(c0, 0.f); sm[r + 1] = fmaxf(c1, 0.f);
                sm[r + 8 * ACT_STRIDE] = fmaxf(c2, 0.f); sm[r + 8 * ACT_STRIDE + 1] = fmaxf(c3, 0.f);
            }
        __syncwarp();
    }

    // =============== layer 1b: [32,64]x[64,16], no relu, single tf32 ===============
    {
        unsigned au[2][8][4];
        #pragma unroll
        for (int mt = 0; mt < 2; mt++)
            #pragma unroll
            for (int kt = 0; kt < 8; kt++) {
                int r = actB + (mt * 16 + g) * ACT_STRIDE + kt * 8;
                au[mt][kt][0] = f2tf(sm[r + tg]);
                au[mt][kt][1] = f2tf(sm[r + 8 * ACT_STRIDE + tg]);
                au[mt][kt][2] = f2tf(sm[r + tg + 4]);
                au[mt][kt][3] = f2tf(sm[r + 8 * ACT_STRIDE + tg + 4]);
            }
        __syncwarp();
        #pragma unroll
        for (int mt = 0; mt < 2; mt++)
            #pragma unroll
            for (int nt = 0; nt < 2; nt++) {
                float c0 = sm[OB1B + nt * 8 + 2 * tg], c1 = sm[OB1B + nt * 8 + 2 * tg + 1];
                float c2 = c0, c3 = c1;
                #pragma unroll
                for (int kt = 0; kt < 8; kt++) {
                    int wb = OW1BT + (nt * 8 + g) * 68 + kt * 8 + tg;
                    mma_tf32(c0, c1, c2, c3,
                             au[mt][kt][0], au[mt][kt][1], au[mt][kt][2], au[mt][kt][3],
                             su[wb], su[wb + 4]);
                }
                int r = actB + (mt * 16 + g) * ACT_STRIDE + nt * 8 + 2 * tg;
                sm[r] = c0; sm[r + 1] = c1;
                sm[r + 8 * ACT_STRIDE] = c2; sm[r + 8 * ACT_STRIDE + 1] = c3;
            }
        __syncwarp();
    }

    // =============== sigma + z = [h(16), d(3), posenc(24), pad to 48] ===============
    float sigma;
    {
        float h0v = sm[actB + ln * ACT_STRIDE + 0];
        sigma = mask ? __expf(h0v) : 0.0f;
        int zr = actB + ln * ACT_STRIDE;
        sm[zr + 16] = d0; sm[zr + 17] = d1; sm[zr + 18] = d2;
        #pragma unroll
        for (int q = 0; q < 4; q++) {
            float m = (float)(1 << q);
            float s, c;
            __sincosf(m * d0, &s, &c); sm[zr + 19 + 6 * q + 0] = s; sm[zr + 22 + 6 * q + 0] = c;
            __sincosf(m * d1, &s, &c); sm[zr + 19 + 6 * q + 1] = s; sm[zr + 22 + 6 * q + 1] = c;
            __sincosf(m * d2, &s, &c); sm[zr + 19 + 6 * q + 2] = s; sm[zr + 22 + 6 * q + 2] = c;
        }
        sm[zr + 43] = 0.f; sm[zr + 44] = 0.f; sm[zr + 45] = 0.f;
        sm[zr + 46] = 0.f; sm[zr + 47] = 0.f;
    }
    __syncwarp();

    // =============== layer 2a: [32,48]x[48,64], relu, tf32 x3 ===============
    {
        float cf[64];
        #pragma unroll
        for (int mt = 0; mt < 2; mt++) {
            unsigned ah[6][4], al[6][4];
            #pragma unroll
            for (int kt = 0; kt < 6; kt++) {
                int r = actB + (mt * 16 + g) * ACT_STRIDE + kt * 8;
                #pragma unroll
                for (int q = 0; q < 4; q++) {
                    int off = (q & 1) * 8 * ACT_STRIDE + (q >> 1) * 4 + tg;
                    float f = sm[r + off];
                    unsigned h = f2tf(f);
                    ah[kt][q] = h;
                    al[kt][q] = f2tf(f - __uint_as_float(h));
                }
            }
            #pragma unroll
            for (int nt = 0; nt < 8; nt++) {
                float c0 = sm[OB2A + nt * 8 + 2 * tg], c1 = sm[OB2A + nt * 8 + 2 * tg + 1];
                float c2 = c0, c3 = c1;
                #pragma unroll
                for (int kt = 0; kt < 6; kt++) {
                    int wh = OW2ATH + (nt * 8 + g) * 52 + kt * 8 + tg;
                    int wl = OW2ATL + (nt * 8 + g) * 52 + kt * 8 + tg;
                    unsigned bh0 = su[wh], bh1 = su[wh + 4];
                    unsigned bl0 = su[wl], bl1 = su[wl + 4];
                    mma_tf32(c0, c1, c2, c3, ah[kt][0], ah[kt][1], ah[kt][2], ah[kt][3], bh0, bh1);
                    mma_tf32(c0, c1, c2, c3, ah[kt][0], ah[kt][1], ah[kt][2], ah[kt][3], bl0, bl1);
                    mma_tf32(c0, c1, c2, c3, al[kt][0], al[kt][1], al[kt][2], al[kt][3], bh0, bh1);
                }
                cf[(mt * 8 + nt) * 4 + 0] = c0; cf[(mt * 8 + nt) * 4 + 1] = c1;
                cf[(mt * 8 + nt) * 4 + 2] = c2; cf[(mt * 8 + nt) * 4 + 3] = c3;
            }
        }
        __syncwarp();
        #pragma unroll
        for (int mt = 0; mt < 2; mt++)
            #pragma unroll
            for (int nt = 0; nt < 8; nt++) {
                int r = actB + (mt * 16 + g) * ACT_STRIDE + nt * 8 + 2 * tg;
                sm[r]     = fmaxf(cf[(mt * 8 + nt) * 4 + 0], 0.f);
                sm[r + 1] = fmaxf(cf[(mt * 8 + nt) * 4 + 1], 0.f);
                sm[r + 8 * ACT_STRIDE]     = fmaxf(cf[(mt * 8 + nt) * 4 + 2], 0.f);
                sm[r + 8 * ACT_STRIDE + 1] = fmaxf(cf[(mt * 8 + nt) * 4 + 3], 0.f);
            }
        __syncwarp();
    }

    // =============== layer 2b: [32,64]x[64,64], relu, tf32 x3 ===============
    {
        float cf[64];
        #pragma unroll
        for (int mt = 0; mt < 2; mt++) {
            unsigned ah[8][4], al[8][4];
            #pragma unroll
            for (int kt = 0; kt < 8; kt++) {
                int r = actB + (mt * 16 + g) * ACT_STRIDE + kt * 8;
                #pragma unroll
                for (int q = 0; q < 4; q++) {
                    int off = (q & 1) * 8 * ACT_STRIDE + (q >> 1) * 4 + tg;
                    float f = sm[r + off];
                    unsigned h = f2tf(f);
                    ah[kt][q] = h;
                    al[kt][q] = f2tf(f - __uint_as_float(h));
                }
            }
            #pragma unroll
            for (int nt = 0; nt < 8; nt++) {
                float c0 = sm[OB2B + nt * 8 + 2 * tg], c1 = sm[OB2B + nt * 8 + 2 * tg + 1];
                float c2 = c0, c3 = c1;
                #pragma unroll
                for (int kt = 0; kt < 8; kt++) {
                    int wh = OW2BTH + (nt * 8 + g) * 68 + kt * 8 + tg;
                    int wl = OW2BTL + (nt * 8 + g) * 68 + kt * 8 + tg;
                    unsigned bh0 = su[wh], bh1 = su[wh + 4];
                    unsigned bl0 = su[wl], bl1 = su[wl + 4];
                    mma_tf32(c0, c1, c2, c3, ah[kt][0], ah[kt][1], ah[kt][2], ah[kt][3], bh0, bh1);
                    mma_tf32(c0, c1, c2, c3, ah[kt][0], ah[kt][1], ah[kt][2], ah[kt][3], bl0, bl1);
                    mma_tf32(c0, c1, c2, c3, al[kt][0], al[kt][1], al[kt][2], al[kt][3], bh0, bh1);
                }
                cf[(mt * 8 + nt) * 4 + 0] = c0; cf[(mt * 8 + nt) * 4 + 1] = c1;
                cf[(mt * 8 + nt) * 4 + 2] = c2; cf[(mt * 8 + nt) * 4 + 3] = c3;
            }
        }
        __syncwarp();
        #pragma unroll
        for (int mt = 0; mt < 2; mt++)
            #pragma unroll
            for (int nt = 0; nt < 8; nt++) {
                int r = actB + (mt * 16 + g) * ACT_STRIDE + nt * 8 + 2 * tg;
                sm[r]     = fmaxf(cf[(mt * 8 + nt) * 4 + 0], 0.f);
                sm[r + 1] = fmaxf(cf[(mt * 8 + nt) * 4 + 1], 0.f);
                sm[r + 8 * ACT_STRIDE]     = fmaxf(cf[(mt * 8 + nt) * 4 + 2], 0.f);
                sm[r + 8 * ACT_STRIDE + 1] = fmaxf(cf[(mt * 8 + nt) * 4 + 3], 0.f);
            }
        __syncwarp();
    }

    // =============== layer 2c: 64 -> 3, sigmoid (scalar fp32) ===============
    {
        float c0 = sm[OB2C + 0], c1 = sm[OB2C + 1], c2 = sm[OB2C + 2];
        int zr = actB + ln * ACT_STRIDE;
        #pragma unroll 8
        for (int k = 0; k < 64; k++) {
            float v = sm[zr + k];
            c0 = fmaf(v, sm[OW2C + 3 * k + 0], c0);
            c1 = fmaf(v, sm[OW2C + 3 * k + 1], c1);
            c2 = fmaf(v, sm[OW2C + 3 * k + 2], c2);
        }
        c0 = 1.0f / (1.0f + __expf(-c0));
        c1 = 1.0f / (1.0f + __expf(-c1));
        c2 = 1.0f / (1.0f + __expf(-c2));

        if (valid) {
            out[3 * pt + 0] = mask ? c0 : 0.0f;
            out[3 * pt + 1] = mask ? c1 : 0.0f;
            out[3 * pt + 2] = mask ? c2 : 0.0f;
            out[3 * n + pt] = sigma;
        }
    }
}

extern "C" void kernel_launch(void* const* d_in, const int* in_sizes, int n_in,
                              void* d_out, int out_size) {
    const float* x      = (const float*)d_in[0];
    const float* dd     = (const float*)d_in[1];
    const float* tables = (const float*)d_in[2];

    int n = in_sizes[0] / 3;

    int t1 = 256;
    ngp_gather_kernel<<<(n + t1 - 1) / t1, t1>>>(x, tables, n);

    cudaFuncSetAttribute(ngp_mlp_kernel,
                         cudaFuncAttributeMaxDynamicSharedMemorySize, SMEM_BYTES);
    int blocks = (n + 127) / 128;
    ngp_mlp_kernel<<<blocks, 128, SMEM_BYTES>>>(
        x, dd,
        (const float*)d_in[3], (const float*)d_in[4],
        (const float*)d_in[5], (const float*)d_in[6],
        (const float*)d_in[7], (const float*)d_in[8],
        (const float*)d_in[9], (const float*)d_in[10],
        (const float*)d_in[11], (const float*)d_in[12],
        (float*)d_out, n);
}